// round 4
// baseline (speedup 1.0000x reference)
#include <cuda_runtime.h>

#define N_NODES 50000
#define N_EDGES 200000
#define IN_C    32
#define HID     32
#define OUT_C   16
#define EDGE_DIM 8
#define LN_EPS  1e-5f

typedef unsigned long long u64;

__device__ float g_agg[N_NODES * HID];

__device__ __forceinline__ u64 ffma2(u64 a, u64 b, u64 c) {
    u64 d;
    asm("fma.rn.f32x2 %0, %1, %2, %3;" : "=l"(d) : "l"(a), "l"(b), "l"(c));
    return d;
}
__device__ __forceinline__ u64 dup2(float s) {
    unsigned u = __float_as_uint(s);
    return ((u64)u << 32) | (u64)u;
}
__device__ __forceinline__ u64 pack2(float lo, float hi) {
    return ((u64)__float_as_uint(hi) << 32) | (u64)__float_as_uint(lo);
}
// packed relu: clear each 32-bit half whose sign bit is set (ALU pipe)
__device__ __forceinline__ u64 relu2(u64 v) {
    unsigned lo = (unsigned)v, hi = (unsigned)(v >> 32);
    lo &= ~(unsigned)((int)lo >> 31);
    hi &= ~(unsigned)((int)hi >> 31);
    return ((u64)hi << 32) | (u64)lo;
}

__global__ __launch_bounds__(256) void zero_agg_kernel() {
    int i = blockIdx.x * blockDim.x + threadIdx.x;
    const int n4 = N_NODES * HID / 4;
    float4* p = (float4*)g_agg;
    const float4 z = make_float4(0.f, 0.f, 0.f, 0.f);
    for (; i < n4; i += gridDim.x * blockDim.x) p[i] = z;
}

// ---------------------------------------------------------------------------
// Edge kernel, f32x2-packed + software-pipelined gather.
// Warp: lane l -> p = l & 15 owns output pair (2p, 2p+1); eh = l >> 4 selects
// a 4-edge subset of the warp's 8-edge group. Both half-warps read identical
// w smem words (broadcast), amortizing w LDS over 8 edges.
// x[src] rows are prefetched into registers one group ahead, then staged to
// smem as PRE-DUPLICATED u64 pairs so the inner-loop xv is one LDS.64.
// ---------------------------------------------------------------------------
__global__ __launch_bounds__(256) void edge_kernel(
    const float* __restrict__ x,
    const int*   __restrict__ edge_index,
    const float* __restrict__ edge_attr,
    const float* __restrict__ nn_w,
    const float* __restrict__ nn_b)
{
    __shared__ u64 sw2[IN_C * EDGE_DIM * 16];  // 4096 u64 = 32 KB
    __shared__ u64 sb2[IN_C * 16];             //  512 u64 =  4 KB
    __shared__ u64 xs2[8][8][IN_C];            // warp x edge x feat (dup'd) = 16 KB

    const int tid = threadIdx.x;

    // stage nn_w transposed+packed: global [d][i*32 + 2p{,+1}] -> sw2[(i*8+d)*16+p]
    for (int idx = tid; idx < EDGE_DIM * 512; idx += 256) {
        const int d = idx >> 9;
        const int j = idx & 511;
        const int i = j >> 4;
        const int p = j & 15;
        const float2 v = *(const float2*)(nn_w + d * (IN_C * HID) + i * HID + 2 * p);
        sw2[(i * EDGE_DIM + d) * 16 + p] = pack2(v.x, v.y);
    }
    for (int idx = tid; idx < 512; idx += 256) {
        const int i = idx >> 4;
        const int p = idx & 15;
        const float2 v = *(const float2*)(nn_b + i * HID + 2 * p);
        sb2[i * 16 + p] = pack2(v.x, v.y);
    }
    __syncthreads();

    const int lane = tid & 31;
    const int p    = lane & 15;
    const int eh   = lane >> 4;
    const int warp = tid >> 5;
    const int gwarp = blockIdx.x * 8 + warp;
    const int warpsTotal = gridDim.x * 8;
    const int nGroups = N_EDGES / 8;  // 25000, exact

    int g = gwarp;
    float xr[8];
    if (g < nGroups) {
        #pragma unroll
        for (int e = 0; e < 8; ++e) {
            const int s = edge_index[g * 8 + e];       // uniform -> bcast LDG
            xr[e] = x[(size_t)s * IN_C + lane];         // coalesced row
        }
    }

    while (g < nGroups) {
        const int gn = g + warpsTotal;

        // stage prefetched x rows as packed duplicates
        #pragma unroll
        for (int e = 0; e < 8; ++e)
            xs2[warp][e][lane] = dup2(xr[e]);
        __syncwarp();

        // my half's 4 edges: dst + packed-duplicated edge_attr
        const int eb = g * 8 + eh * 4;
        int dst[4];
        u64 ea2[4][8];
        #pragma unroll
        for (int e = 0; e < 4; ++e) {
            dst[e] = edge_index[N_EDGES + eb + e];
            const float4 lo = *(const float4*)(edge_attr + (size_t)(eb + e) * EDGE_DIM);
            const float4 hi = *(const float4*)(edge_attr + (size_t)(eb + e) * EDGE_DIM + 4);
            ea2[e][0] = dup2(lo.x); ea2[e][1] = dup2(lo.y);
            ea2[e][2] = dup2(lo.z); ea2[e][3] = dup2(lo.w);
            ea2[e][4] = dup2(hi.x); ea2[e][5] = dup2(hi.y);
            ea2[e][6] = dup2(hi.z); ea2[e][7] = dup2(hi.w);
        }

        // prefetch next group's x rows (latency hidden under compute below)
        if (gn < nGroups) {
            #pragma unroll
            for (int e = 0; e < 8; ++e) {
                const int s = edge_index[gn * 8 + e];
                xr[e] = x[(size_t)s * IN_C + lane];
            }
        }

        u64 msg2[4] = {0ull, 0ull, 0ull, 0ull};

        #pragma unroll 8
        for (int i = 0; i < IN_C; ++i) {
            u64 w[8];
            #pragma unroll
            for (int d = 0; d < 8; ++d) w[d] = sw2[(i * 8 + d) * 16 + p];
            const u64 b = sb2[i * 16 + p];
            #pragma unroll
            for (int e = 0; e < 4; ++e) {
                const u64 xv = xs2[warp][eh * 4 + e][i];   // bcast LDS.64
                u64 a = b;
                #pragma unroll
                for (int d = 0; d < 8; ++d) a = ffma2(ea2[e][d], w[d], a);
                a = relu2(a);                    // W[e][i][2p,2p+1]
                msg2[e] = ffma2(xv, a, msg2[e]);
            }
        }

        #pragma unroll
        for (int e = 0; e < 4; ++e) {
            float* base = &g_agg[(size_t)dst[e] * HID + 2 * p];
            atomicAdd(base,     __uint_as_float((unsigned)msg2[e]));
            atomicAdd(base + 1, __uint_as_float((unsigned)(msg2[e] >> 32)));
        }
        __syncwarp();  // xs2 reads done before next overwrite
        g = gn;
    }
}

// ---------------------------------------------------------------------------
// Node kernel: h = agg + x@root + bias; LayerNorm; ReLU; out = h@lin_w + lin_b
// ---------------------------------------------------------------------------
__global__ __launch_bounds__(256) void node_kernel(
    const float* __restrict__ x,
    const float* __restrict__ root,
    const float* __restrict__ bias,
    const float* __restrict__ norm_w,
    const float* __restrict__ norm_b,
    const float* __restrict__ lin_w,
    const float* __restrict__ lin_b,
    float* __restrict__ out)
{
    __shared__ float root_s[IN_C * HID];
    __shared__ float lw_s[HID * OUT_C];
    __shared__ float bias_s[HID], nw_s[HID], nb_s[HID], lb_s[OUT_C];

    const int tid = threadIdx.x;
    for (int i = tid; i < IN_C * HID; i += 256) root_s[i] = root[i];
    for (int i = tid; i < HID * OUT_C; i += 256) lw_s[i] = lin_w[i];
    if (tid < HID) { bias_s[tid] = bias[tid]; nw_s[tid] = norm_w[tid]; nb_s[tid] = norm_b[tid]; }
    if (tid < OUT_C) lb_s[tid] = lin_b[tid];
    __syncthreads();

    int n = blockIdx.x * blockDim.x + threadIdx.x;
    const int stride = gridDim.x * blockDim.x;
    for (; n < N_NODES; n += stride) {
        float h[HID];
        const float4* aggp = (const float4*)(g_agg + (size_t)n * HID);
        #pragma unroll
        for (int q = 0; q < HID / 4; ++q) {
            float4 v = aggp[q];
            h[q * 4 + 0] = v.x + bias_s[q * 4 + 0];
            h[q * 4 + 1] = v.y + bias_s[q * 4 + 1];
            h[q * 4 + 2] = v.z + bias_s[q * 4 + 2];
            h[q * 4 + 3] = v.w + bias_s[q * 4 + 3];
        }

        const float4* xp = (const float4*)(x + (size_t)n * IN_C);
        #pragma unroll
        for (int q = 0; q < IN_C / 4; ++q) {
            float4 xv4 = xp[q];
            float xv[4] = {xv4.x, xv4.y, xv4.z, xv4.w};
            #pragma unroll
            for (int s = 0; s < 4; ++s) {
                const int i = q * 4 + s;
                #pragma unroll
                for (int o = 0; o < HID; ++o)
                    h[o] = fmaf(xv[s], root_s[i * HID + o], h[o]);
            }
        }

        float mu = 0.f;
        #pragma unroll
        for (int o = 0; o < HID; ++o) mu += h[o];
        mu *= (1.0f / HID);
        float var = 0.f;
        #pragma unroll
        for (int o = 0; o < HID; ++o) { float dd = h[o] - mu; var = fmaf(dd, dd, var); }
        var *= (1.0f / HID);
        const float inv = rsqrtf(var + LN_EPS);
        #pragma unroll
        for (int o = 0; o < HID; ++o)
            h[o] = fmaxf(fmaf((h[o] - mu) * inv, nw_s[o], nb_s[o]), 0.f);

        float res[OUT_C];
        #pragma unroll
        for (int oo = 0; oo < OUT_C; ++oo) res[oo] = lb_s[oo];
        #pragma unroll
        for (int k = 0; k < HID; ++k) {
            const float hv = h[k];
            #pragma unroll
            for (int oo = 0; oo < OUT_C; ++oo)
                res[oo] = fmaf(hv, lw_s[k * OUT_C + oo], res[oo]);
        }

        float4* op = (float4*)(out + (size_t)n * OUT_C);
        #pragma unroll
        for (int q = 0; q < OUT_C / 4; ++q)
            op[q] = make_float4(res[q * 4 + 0], res[q * 4 + 1], res[q * 4 + 2], res[q * 4 + 3]);
    }
}

extern "C" void kernel_launch(void* const* d_in, const int* in_sizes, int n_in,
                              void* d_out, int out_size) {
    const float* x          = (const float*)d_in[0];
    const int*   edge_index = (const int*)  d_in[1];
    const float* edge_attr  = (const float*)d_in[2];
    const float* nn_w       = (const float*)d_in[3];
    const float* nn_b       = (const float*)d_in[4];
    const float* root       = (const float*)d_in[5];
    const float* bias       = (const float*)d_in[6];
    const float* norm_w     = (const float*)d_in[7];
    const float* norm_b     = (const float*)d_in[8];
    const float* lin_w      = (const float*)d_in[9];
    const float* lin_b      = (const float*)d_in[10];
    float* out = (float*)d_out;

    zero_agg_kernel<<<296, 256>>>();
    edge_kernel<<<592, 256>>>(x, edge_index, edge_attr, nn_w, nn_b);
    node_kernel<<<(N_NODES + 255) / 256, 256>>>(x, root, bias, norm_w, norm_b,
                                                lin_w, lin_b, out);
}